// round 1
// baseline (speedup 1.0000x reference)
#include <cuda_runtime.h>
#include <cuda_bf16.h>
#include <math.h>

// Problem constants (fixed by reference)
#define D_MODEL   2048
#define NUM_HEADS 16
#define QGROUPS   4
#define HEAD_DIM  128
#define M_PER_G   (NUM_HEADS / QGROUPS)   // 4
#define BATCH     2
#define SEQ       2048
#define ROWS      (BATCH * SEQ)           // 4096
#define KV_COLS   (QGROUPS * HEAD_DIM)    // 512

// ---------------- scratch (device globals; no cudaMalloc allowed) ------------
__device__ float g_q[ROWS * D_MODEL];     // 33.5 MB
__device__ float g_k[ROWS * KV_COLS];     //  8.4 MB
__device__ float g_v[ROWS * KV_COLS];     //  8.4 MB
__device__ float g_attn[ROWS * D_MODEL];  // 33.5 MB

// ============================================================================
// Generic GEMM + bias:  C[M,N] = A[M,K] @ B[K,N] + bias[N]
// 64x64 block tile, BK=16, 256 threads, 4x4 per-thread micro-tile.
// As stored transposed ([BK][BM]) so fragments load as LDS.128.
// All dims are multiples of 64/16 in this problem (no bounds checks).
// ============================================================================
#define BM 64
#define BN 64
#define BK 16

__global__ __launch_bounds__(256) void gemm_bias_kernel(
    const float* __restrict__ A, const float* __restrict__ B,
    const float* __restrict__ bias, float* __restrict__ C,
    int M, int N, int K)
{
    __shared__ float As[BK][BM];
    __shared__ float Bs[BK][BN];

    const int tid = threadIdx.x;
    const int tx = tid & 15;        // 0..15
    const int ty = tid >> 4;        // 0..15
    const int brow = blockIdx.y * BM;
    const int bcol = blockIdx.x * BN;

    // global->shared load indices
    const int arow  = tid >> 2;          // 0..63
    const int acol4 = (tid & 3) * 4;     // 0,4,8,12
    const int bkrow = tid >> 4;          // 0..15
    const int bcol4 = (tid & 15) * 4;

    float acc[4][4] = {};

    for (int k0 = 0; k0 < K; k0 += BK) {
        float4 av = *(const float4*)&A[(size_t)(brow + arow) * K + k0 + acol4];
        As[acol4 + 0][arow] = av.x;
        As[acol4 + 1][arow] = av.y;
        As[acol4 + 2][arow] = av.z;
        As[acol4 + 3][arow] = av.w;
        *(float4*)&Bs[bkrow][bcol4] =
            *(const float4*)&B[(size_t)(k0 + bkrow) * N + bcol + bcol4];
        __syncthreads();

        #pragma unroll
        for (int kk = 0; kk < BK; kk++) {
            float4 a = *(const float4*)&As[kk][ty * 4];
            float4 b = *(const float4*)&Bs[kk][tx * 4];
            acc[0][0] += a.x * b.x; acc[0][1] += a.x * b.y; acc[0][2] += a.x * b.z; acc[0][3] += a.x * b.w;
            acc[1][0] += a.y * b.x; acc[1][1] += a.y * b.y; acc[1][2] += a.y * b.z; acc[1][3] += a.y * b.w;
            acc[2][0] += a.z * b.x; acc[2][1] += a.z * b.y; acc[2][2] += a.z * b.z; acc[2][3] += a.z * b.w;
            acc[3][0] += a.w * b.x; acc[3][1] += a.w * b.y; acc[3][2] += a.w * b.z; acc[3][3] += a.w * b.w;
        }
        __syncthreads();
    }

    #pragma unroll
    for (int i = 0; i < 4; i++) {
        const int r = brow + ty * 4 + i;
        #pragma unroll
        for (int j = 0; j < 4; j++) {
            const int c = bcol + tx * 4 + j;
            C[(size_t)r * N + c] = acc[i][j] + bias[c];
        }
    }
}

// ============================================================================
// Flash attention (fp32, online softmax).
// grid = (SEQ/Br, BATCH*NUM_HEADS), block = 256 threads.
// Br=Bc=64, hd=128. Q,K stored transposed in smem for LDS.128 frag loads.
// Each block: Q tile fixed; loop over 32 key tiles.
// O accumulator: thread t owns row (t>>2), dims [(t&3)*32, +32) in registers.
// ============================================================================
#define Br 64
#define Bc 64
#define HD 128
#define ATTN_SMEM ((HD*Br + HD*Bc + Bc*HD + Br*Bc) * (int)sizeof(float)) // 112 KB

__global__ __launch_bounds__(256) void attn_kernel(
    const float* __restrict__ Q,   // [ROWS, D_MODEL]
    const float* __restrict__ K,   // [ROWS, KV_COLS]
    const float* __restrict__ V,   // [ROWS, KV_COLS]
    float* __restrict__ O)         // [ROWS, D_MODEL]
{
    extern __shared__ float sm[];
    float* Qt = sm;                 // [HD][Br]  (Qt[kk][r])
    float* Kt = Qt + HD * Br;       // [HD][Bc]  (Kt[kk][c])
    float* Vs = Kt + HD * Bc;       // [Bc][HD]
    float* S  = Vs + Bc * HD;       // [Br][Bc]

    const int tid = threadIdx.x;
    const int bh = blockIdx.y;                  // b*NUM_HEADS + h
    const int b  = bh / NUM_HEADS;
    const int h  = bh % NUM_HEADS;
    const int g  = h / M_PER_G;
    const int q0 = blockIdx.x * Br;

    const float qscale = 0.08838834764831845f;  // 1/sqrt(128)

    // ---- load Q tile (transposed, pre-scaled) ----
    {
        const int r   = tid >> 2;           // 0..63
        const int kk0 = (tid & 3) * 4;      // 0,4,8,12
        const float* qrow = &Q[(size_t)(b * SEQ + q0 + r) * D_MODEL + h * HD];
        #pragma unroll
        for (int it = 0; it < 8; it++) {
            const int kk = kk0 + it * 16;
            float4 qv = *(const float4*)&qrow[kk];
            Qt[(kk + 0) * Br + r] = qv.x * qscale;
            Qt[(kk + 1) * Br + r] = qv.y * qscale;
            Qt[(kk + 2) * Br + r] = qv.z * qscale;
            Qt[(kk + 3) * Br + r] = qv.w * qscale;
        }
    }

    // per-thread softmax state (replicated x4 per row)
    const int r     = tid >> 2;        // row 0..63
    const int lane4 = tid & 3;
    const int dseg  = lane4 * 32;

    float m_i = -1e30f;
    float l_i = 0.0f;
    float o[32];
    #pragma unroll
    for (int d = 0; d < 32; d++) o[d] = 0.0f;

    const int tx = tid & 15;
    const int ty = tid >> 4;

    for (int s0 = 0; s0 < SEQ; s0 += Bc) {
        __syncthreads();  // prior PV done with Vs/S; Qt ready on first iter

        // ---- load K tile (transposed) and V tile (natural) ----
        {
            const int j   = tid >> 2;
            const int c0  = (tid & 3) * 4;
            const float* krow = &K[(size_t)(b * SEQ + s0 + j) * KV_COLS + g * HD];
            const float* vrow = &V[(size_t)(b * SEQ + s0 + j) * KV_COLS + g * HD];
            #pragma unroll
            for (int it = 0; it < 8; it++) {
                const int kk = c0 + it * 16;
                float4 kv = *(const float4*)&krow[kk];
                Kt[(kk + 0) * Bc + j] = kv.x;
                Kt[(kk + 1) * Bc + j] = kv.y;
                Kt[(kk + 2) * Bc + j] = kv.z;
                Kt[(kk + 3) * Bc + j] = kv.w;
                *(float4*)&Vs[j * HD + kk] = *(const float4*)&vrow[kk];
            }
        }
        __syncthreads();

        // ---- S = (Q*scale) @ K^T : thread (ty,tx) -> S[4ty..][4tx..] ----
        {
            float acc[4][4] = {};
            #pragma unroll 8
            for (int kk = 0; kk < HD; kk++) {
                float4 a = *(const float4*)&Qt[kk * Br + ty * 4];
                float4 bb = *(const float4*)&Kt[kk * Bc + tx * 4];
                acc[0][0] += a.x * bb.x; acc[0][1] += a.x * bb.y; acc[0][2] += a.x * bb.z; acc[0][3] += a.x * bb.w;
                acc[1][0] += a.y * bb.x; acc[1][1] += a.y * bb.y; acc[1][2] += a.y * bb.z; acc[1][3] += a.y * bb.w;
                acc[2][0] += a.z * bb.x; acc[2][1] += a.z * bb.y; acc[2][2] += a.z * bb.z; acc[2][3] += a.z * bb.w;
                acc[3][0] += a.w * bb.x; acc[3][1] += a.w * bb.y; acc[3][2] += a.w * bb.z; acc[3][3] += a.w * bb.w;
            }
            #pragma unroll
            for (int i = 0; i < 4; i++)
                #pragma unroll
                for (int j = 0; j < 4; j++)
                    S[(ty * 4 + i) * Bc + tx * 4 + j] = acc[i][j];
        }
        __syncthreads();

        // ---- online softmax (4 lanes per row) + PV accumulate ----
        {
            const int jbase = lane4 * 16;
            float tmax = -1e30f;
            #pragma unroll
            for (int jj = 0; jj < 16; jj++)
                tmax = fmaxf(tmax, S[r * Bc + jbase + jj]);
            tmax = fmaxf(tmax, __shfl_xor_sync(0xffffffffu, tmax, 1));
            tmax = fmaxf(tmax, __shfl_xor_sync(0xffffffffu, tmax, 2));

            const float mnew = fmaxf(m_i, tmax);
            const float corr = __expf(m_i - mnew);

            float psum = 0.0f;
            #pragma unroll
            for (int jj = 0; jj < 16; jj++) {
                const int idx = r * Bc + jbase + jj;
                float p = __expf(S[idx] - mnew);
                S[idx] = p;
                psum += p;
            }
            psum += __shfl_xor_sync(0xffffffffu, psum, 1);
            psum += __shfl_xor_sync(0xffffffffu, psum, 2);

            l_i = l_i * corr + psum;
            m_i = mnew;
            #pragma unroll
            for (int d = 0; d < 32; d++) o[d] *= corr;

            __syncwarp();  // all 4 lanes' P writes visible within the warp

            #pragma unroll 4
            for (int j = 0; j < Bc; j++) {
                const float p = S[r * Bc + j];
                const float* vrow = &Vs[j * HD + dseg];
                #pragma unroll
                for (int d4 = 0; d4 < 32; d4 += 4) {
                    float4 vv = *(const float4*)&vrow[d4];
                    o[d4 + 0] += p * vv.x;
                    o[d4 + 1] += p * vv.y;
                    o[d4 + 2] += p * vv.z;
                    o[d4 + 3] += p * vv.w;
                }
            }
        }
    }

    // ---- finalize: O = o / l ----
    {
        const float inv_l = 1.0f / l_i;
        float* orow = &O[(size_t)(b * SEQ + q0 + r) * D_MODEL + h * HD + dseg];
        #pragma unroll
        for (int d4 = 0; d4 < 32; d4 += 4) {
            float4 ov;
            ov.x = o[d4 + 0] * inv_l;
            ov.y = o[d4 + 1] * inv_l;
            ov.z = o[d4 + 2] * inv_l;
            ov.w = o[d4 + 3] * inv_l;
            *(float4*)&orow[d4] = ov;
        }
    }
}

// ============================================================================
// Launch
// ============================================================================
extern "C" void kernel_launch(void* const* d_in, const int* in_sizes, int n_in,
                              void* d_out, int out_size)
{
    const float* x  = (const float*)d_in[0];
    const float* Wq = (const float*)d_in[1];
    const float* bq = (const float*)d_in[2];
    const float* Wk = (const float*)d_in[3];
    const float* bk = (const float*)d_in[4];
    const float* Wv = (const float*)d_in[5];
    const float* bv = (const float*)d_in[6];
    const float* Wo = (const float*)d_in[7];
    const float* bo = (const float*)d_in[8];
    float* out = (float*)d_out;

    float *q, *k, *v, *attn;
    cudaGetSymbolAddress((void**)&q,    g_q);
    cudaGetSymbolAddress((void**)&k,    g_k);
    cudaGetSymbolAddress((void**)&v,    g_v);
    cudaGetSymbolAddress((void**)&attn, g_attn);

    // QKV projections
    gemm_bias_kernel<<<dim3(D_MODEL / BN, ROWS / BM), 256>>>(
        x, Wq, bq, q, ROWS, D_MODEL, D_MODEL);
    gemm_bias_kernel<<<dim3(KV_COLS / BN, ROWS / BM), 256>>>(
        x, Wk, bk, k, ROWS, KV_COLS, D_MODEL);
    gemm_bias_kernel<<<dim3(KV_COLS / BN, ROWS / BM), 256>>>(
        x, Wv, bv, v, ROWS, KV_COLS, D_MODEL);

    // Attention
    static bool attr_set = false;
    cudaFuncSetAttribute(attn_kernel,
                         cudaFuncAttributeMaxDynamicSharedMemorySize, ATTN_SMEM);
    (void)attr_set;
    attn_kernel<<<dim3(SEQ / Br, BATCH * NUM_HEADS), 256, ATTN_SMEM>>>(q, k, v, attn);

    // Output projection
    gemm_bias_kernel<<<dim3(D_MODEL / BN, ROWS / BM), 256>>>(
        attn, Wo, bo, out, ROWS, D_MODEL, D_MODEL);
}